// round 16
// baseline (speedup 1.0000x reference)
#include <cuda_runtime.h>
#include <cuda_fp16.h>
#include <cstdint>

#define MAX_NODES 100000
#define D_NODE 128
#define D_HID 256
#define N_GRAPHS 64
#define CAP   320          // per-bin edge capacity (mean 128, sd 11 -> safe)
#define NBINS 12512        // ceil(MAX_NODES/64)*8 rounded up

// Scratch (no cudaMalloc allowed)
__device__ int    g_bin_cnt[NBINS];          // edges per 8-node bin
__device__ int    g_bin_lst[NBINS * CAP];    // packed (edge_id<<3)|(col&7)
__device__ float  g_ug[N_GRAPHS * D_HID];    // u @ W1[256:272] + b1
__device__ int    g_batch[MAX_NODES];        // graph id per node (int32)
__device__ __half g_W1h[8 * 256 * 32];       // W1[0:256] as [chunk][n][k32] fp16
__device__ __half g_W2h[8 * 128 * 32];       // W2 as [chunk][n][k32] fp16
__device__ uint4  g_aggh4[MAX_NODES * 16];   // agg as fp16 [node][128] (25.6MB)

// ---------------------------------------------------------------------------
// helpers
// ---------------------------------------------------------------------------
// D += A @ B  (m16n8k16 fp16 operands, fp32 accum)
#define MMA16(d, a, b0_, b1_)                                                  \
    asm volatile(                                                              \
        "mma.sync.aligned.m16n8k16.row.col.f32.f16.f16.f32 "                   \
        "{%0,%1,%2,%3}, {%4,%5,%6,%7}, {%8,%9}, {%0,%1,%2,%3};"                \
        : "+f"((d)[0]), "+f"((d)[1]), "+f"((d)[2]), "+f"((d)[3])               \
        : "r"((a)[0]), "r"((a)[1]), "r"((a)[2]), "r"((a)[3]),                  \
          "r"(b0_), "r"(b1_))

// 4x 8x8 fp16 tiles from shared (sm_75+ baseline)
#define LDMX4(r0, r1, r2, r3, addr)                                            \
    asm volatile(                                                              \
        "ldmatrix.sync.aligned.m8n8.x4.shared.b16 {%0,%1,%2,%3}, [%4];"        \
        : "=r"(r0), "=r"(r1), "=r"(r2), "=r"(r3) : "r"(addr))

__device__ __forceinline__ uint32_t pack2(float a, float b) {
    __half2 h = __floats2half2_rn(a, b);          // x=a (low), y=b (high)
    return *(uint32_t*)&h;
}

// SMEM pitches in 32-bit words. PAW=132: ldmatrix A phases hit banks 4r+c,
// all distinct (m-block offset 16*132 = 0 mod 32 banks). PBW=20: B row banks
// 20n mod 32 distinct over 16 consecutive n. Conflict-free.
#define PAW 132
#define PBW 20

// per-block int64-vs-int32 detect: odd 32-bit words of first 128 int64s are 0
__device__ __forceinline__ int detect_is64(const unsigned* w, int tid, int* s_flag) {
    if (tid < 32) {
        unsigned bad = 0;
#pragma unroll
        for (int j = 0; j < 4; ++j) bad |= w[8 * tid + 2 * j + 1];
        unsigned any = __ballot_sync(0xffffffffu, bad != 0u);
        if (tid == 0) *s_flag = (any == 0u);
    }
    __syncthreads();
    return *s_flag;
}

// ---------------------------------------------------------------------------
// Kernel 1: prep = zero bins + convert batch + ug + fp16 weight transpose
// ---------------------------------------------------------------------------
__global__ void prep_kernel(const void* __restrict__ ei,
                            const void* __restrict__ batch,
                            const float* __restrict__ u,
                            const float* __restrict__ W1,
                            const float* __restrict__ b1,
                            const float* __restrict__ W2,
                            int N, int nb_conv) {
    __shared__ int s_flag;
    const int bx = blockIdx.x;
    const int tid = threadIdx.x;
    if (bx < nb_conv) {                               // bins + batch
        int is64 = detect_is64((const unsigned*)ei, tid, &s_flag);
        int i = bx * 256 + tid;
        if (i < NBINS) g_bin_cnt[i] = 0;
        if (i < N)
            g_batch[i] = is64 ? (int)((const long long*)batch)[i]
                              : ((const int*)batch)[i];
    } else if (bx < nb_conv + N_GRAPHS) {             // ug
        int g = bx - nb_conv, n = tid;
        float s = b1[n];
#pragma unroll
        for (int k = 0; k < 16; ++k)
            s += u[g * 16 + k] * W1[(256 + k) * D_HID + n];
        g_ug[g * D_HID + n] = s;
    } else if (bx < nb_conv + N_GRAPHS + 32) {        // W1 -> fp16 [c][n][k32]
        int j = (bx - nb_conv - N_GRAPHS) * 256 + tid;   // 0..8191
        int c = j >> 10, rem = j & 1023;
        int n = rem >> 2, q = rem & 3;
        uint4 r;
        __half* hp = (__half*)&r;
#pragma unroll
        for (int i = 0; i < 8; ++i)
            hp[i] = __float2half_rn(W1[(size_t)(32 * c + 8 * q + i) * D_HID + n]);
        ((uint4*)g_W1h)[c * 1024 + n * 4 + q] = r;
    } else {                                          // W2 -> fp16 [c][n][k32]
        int j = (bx - nb_conv - N_GRAPHS - 32) * 256 + tid;  // 0..4095
        int c = j >> 9, rem = j & 511;
        int n = rem >> 2, q = rem & 3;
        uint4 r;
        __half* hp = (__half*)&r;
#pragma unroll
        for (int i = 0; i < 8; ++i)
            hp[i] = __float2half_rn(W2[(size_t)(32 * c + 8 * q + i) * D_NODE + n]);
        ((uint4*)g_W2h)[c * 512 + n * 4 + q] = r;
    }
}

// ---------------------------------------------------------------------------
// Kernel 2: fill bins. One thread per edge.
// ---------------------------------------------------------------------------
__global__ void fill_kernel(const void* __restrict__ ei, int E) {
    __shared__ int s_flag;
    int is64 = detect_is64((const unsigned*)ei, threadIdx.x, &s_flag);
    int i = blockIdx.x * 256 + threadIdx.x;
    if (i >= E) return;
    int col = is64 ? (int)((const long long*)ei)[(long long)E + i]
                   : ((const int*)ei)[E + i];
    int b = col >> 3;
    int pos = atomicAdd(&g_bin_cnt[b], 1);
    if (pos < CAP) g_bin_lst[b * CAP + pos] = (i << 3) | (col & 7);
}

// ===========================================================================
// Kernel 3: dedicated aggregation (R15 exact). One warp per 8-node bin,
// spill-proof depth-8 pipeline, no __syncthreads, fp16 out.
// ===========================================================================
__global__ void __launch_bounds__(256)
agg_kernel(const float* __restrict__ ea, int N) {
    __shared__ float sAgg[8 * 8 * 128];          // 8 warps x 8 rows x 128
    const int lane = threadIdx.x & 31;
    const int wid  = threadIdx.x >> 5;
    const int bin  = blockIdx.x * 8 + wid;
    const int nbins = (N + 7) >> 3;
    if (bin >= nbins) return;

    float* myAgg = sAgg + wid * 8 * 128;
#pragma unroll
    for (int r = 0; r < 8; ++r)
        *(float4*)(myAgg + r * 128 + lane * 4) = make_float4(0.f, 0.f, 0.f, 0.f);

    int cnt = g_bin_cnt[bin];
    if (cnt > CAP) cnt = CAP;
    const int* lst = g_bin_lst + (size_t)bin * CAP;

    float4 vb[8]; int rb[8];
#pragma unroll
    for (int j = 0; j < 8; ++j)
        if (j < cnt) {
            int p = lst[j];
            rb[j] = p & 7;
            vb[j] = ((const float4*)ea)[(size_t)(p >> 3) * 32 + lane];
        }
    int i = 0;
    for (; i + 8 <= cnt; i += 8) {
#pragma unroll
        for (int j = 0; j < 8; ++j) {
            float4 v = vb[j];
            int    r = rb[j];
            int nidx = i + 8 + j;
            if (nidx < cnt) {
                int p = lst[nidx];
                rb[j] = p & 7;
                vb[j] = ((const float4*)ea)[(size_t)(p >> 3) * 32 + lane];
            }
            float* d = myAgg + r * 128 + lane * 4;
            float4 o = *(float4*)d;
            o.x += v.x; o.y += v.y; o.z += v.z; o.w += v.w;
            *(float4*)d = o;
        }
    }
#pragma unroll
    for (int j = 0; j < 8; ++j) {
        if (i + j < cnt) {
            float4 v = vb[j];
            float* d = myAgg + rb[j] * 128 + lane * 4;
            float4 o = *(float4*)d;
            o.x += v.x; o.y += v.y; o.z += v.z; o.w += v.w;
            *(float4*)d = o;
        }
    }
#pragma unroll
    for (int r = 0; r < 8; ++r) {
        int node = bin * 8 + r;
        if (node < N) {
            float4 o = *(float4*)(myAgg + r * 128 + lane * 4);
            uint2 h;
            h.x = pack2(o.x, o.y);
            h.y = pack2(o.z, o.w);
            ((uint2*)g_aggh4)[(size_t)node * 32 + lane] = h;
        }
    }
}

// ===========================================================================
// Kernel 4: MLP, fp16 mma + ldmatrix, RETILED 1M x 8N:
// each warp owns all 64 M-rows and a 32-wide (GEMM1) / 16-wide (GEMM2) N
// strip. CTA LDSM per chunk drops 160 -> 96 (GEMM1): B fragments are no
// longer duplicated across M-warps. MMA count and per-output accumulation
// order unchanged -> bit-identical numerics.
// ===========================================================================
__global__ void __launch_bounds__(256, 2)
fused_mlp_mma(const float* __restrict__ x,
              const float* __restrict__ b2,
              float* __restrict__ out, int N) {
    extern __shared__ uint32_t smw[];
    uint32_t* sAw = smw;                        // A fp16: 64 rows x 132 words
    uint32_t* sB0 = smw + 8448;                 // B fp16: 256 x 20 words
    uint32_t* sB1 = smw + 13568;
    __shared__ int s_batch[64];

    const int tid  = threadIdx.x;
    const int lane = tid & 31;
    const int wid  = tid >> 5;       // 0..7 = N-strip id
    const int lq   = lane >> 2;      // 0..7
    const int lr   = lane & 3;       // 0..3
    const int node0 = blockIdx.x * 64;

    // ldmatrix lane-derived addressing (bytes)
    const uint32_t sA_u32  = (uint32_t)__cvta_generic_to_shared(sAw);
    const uint32_t sB0_u32 = (uint32_t)__cvta_generic_to_shared(sB0);
    const uint32_t sB1_u32 = (uint32_t)__cvta_generic_to_shared(sB1);
    // A m-block 0 base; m-block mb at +mb*AMB
    const uint32_t aBase = sA_u32 +
        ((((uint32_t)(lane & 15)) * PAW + ((lane >> 4) * 4)) << 2);
    const uint32_t AMB = (16 * PAW) << 2;
    const uint32_t bRow  = (lane & 7) + ((lane >> 4) << 3);     // 0..15
    const uint32_t bWord = ((lane >> 3) & 1) * 4;

    if (tid < 64) s_batch[tid] = (node0 + tid < N) ? g_batch[node0 + tid] : 0;

    // ---- stage x -> sA words [0,64) per row, RNE fp16 ----
#pragma unroll
    for (int j = 0; j < 4; ++j) {
        int idx = tid + j * 256;          // 0..1023
        int row = idx >> 4, wq = idx & 15;
        int node = node0 + row;
        float4 v0 = make_float4(0.f, 0.f, 0.f, 0.f), v1 = v0;
        if (node < N) {
            v0 = ((const float4*)x)[(size_t)node * 32 + wq * 2];
            v1 = ((const float4*)x)[(size_t)node * 32 + wq * 2 + 1];
        }
        uint4 h;
        h.x = pack2(v0.x, v0.y); h.y = pack2(v0.z, v0.w);
        h.z = pack2(v1.x, v1.y); h.w = pack2(v1.z, v1.w);
        *(uint4*)(sAw + row * PAW + wq * 4) = h;
    }

    // ---- stage agg (already fp16) -> sA words [64,128) per row ----
#pragma unroll
    for (int j = 0; j < 4; ++j) {
        int idx = tid + j * 256;          // 0..1023
        int row = idx >> 4, q = idx & 15;
        int node = node0 + row;
        uint4 v = make_uint4(0u, 0u, 0u, 0u);
        if (node < N) v = g_aggh4[(size_t)node * 16 + q];
        *(uint4*)(sAw + row * PAW + 64 + q * 4) = v;
    }

    // ---- W1 chunk 0 (pre-converted fp16, coalesced) ----
    {
        const uint4* W1v = (const uint4*)g_W1h;
#pragma unroll
        for (int j = 0; j < 4; ++j)
            *(uint4*)(sB0 + tid * PBW + j * 4) = W1v[tid * 4 + j];
    }
    __syncthreads();

    // ================= GEMM1: K=256 halves, 8 chunks of 32 =================
    float acc[4][4][4];                  // [m-block][n-8block][elem]
#pragma unroll
    for (int m = 0; m < 4; ++m)
#pragma unroll
        for (int f = 0; f < 4; ++f)
#pragma unroll
            for (int e = 0; e < 4; ++e) acc[m][f][e] = 0.f;

    const uint4* W1v = (const uint4*)g_W1h;
    for (int c = 0; c < 8; ++c) {
        uint4 pf[4];
        if (c < 7) {
#pragma unroll
            for (int j = 0; j < 4; ++j)
                pf[j] = W1v[(c + 1) * 1024 + tid * 4 + j];
        }
        const uint32_t Bu = (c & 1) ? sB1_u32 : sB0_u32;
#pragma unroll
        for (int s = 0; s < 2; ++s) {
            const uint32_t kwB = (uint32_t)((c * 16 + s * 8) << 2);
            uint32_t a[4][4];
#pragma unroll
            for (int mb = 0; mb < 4; ++mb)
                LDMX4(a[mb][0], a[mb][1], a[mb][2], a[mb][3],
                      aBase + mb * AMB + kwB);
#pragma unroll
            for (int f2 = 0; f2 < 2; ++f2) {
                uint32_t b00, b01, b10, b11;
                uint32_t baddr = Bu +
                    ((((uint32_t)(wid * 32 + f2 * 16) + bRow) * PBW
                      + (uint32_t)(s * 8) + bWord) << 2);
                LDMX4(b00, b01, b10, b11, baddr);
#pragma unroll
                for (int mb = 0; mb < 4; ++mb) {
                    MMA16(acc[mb][2 * f2 + 0], a[mb], b00, b01);
                    MMA16(acc[mb][2 * f2 + 1], a[mb], b10, b11);
                }
            }
        }
        if (c < 7) {
            uint32_t* nbuf = ((c + 1) & 1) ? sB1 : sB0;
#pragma unroll
            for (int j = 0; j < 4; ++j)
                *(uint4*)(nbuf + tid * PBW + j * 4) = pf[j];
        }
        __syncthreads();
    }

    // ---- epilogue 1: h = relu(acc + ug[batch]) -> sA (fp16) ----
#pragma unroll
    for (int mb = 0; mb < 4; ++mb) {
#pragma unroll
        for (int e = 0; e < 2; ++e) {
            int r = mb * 16 + lq + e * 8;
            int g = s_batch[r];
            const float* ugr = g_ug + g * D_HID;
#pragma unroll
            for (int f = 0; f < 4; ++f) {
                int col = wid * 32 + f * 8 + lr * 2;
                float2 ug = *(const float2*)(ugr + col);
                float h0 = fmaxf(acc[mb][f][2 * e + 0] + ug.x, 0.f);
                float h1 = fmaxf(acc[mb][f][2 * e + 1] + ug.y, 0.f);
                sAw[r * PAW + wid * 16 + f * 4 + lr] = pack2(h0, h1);
            }
        }
    }
    // ---- W2 chunk 0 (loads in flight across the h-visibility sync) ----
    {
        const uint4* W2v = (const uint4*)g_W2h;
        int n = tid >> 1, part = (tid & 1) * 2;
        uint4 w0 = W2v[n * 4 + part];
        uint4 w1 = W2v[n * 4 + part + 1];
        __syncthreads();
        *(uint4*)(sB0 + n * PBW + part * 4) = w0;
        *(uint4*)(sB0 + n * PBW + (part + 1) * 4) = w1;
    }
    __syncthreads();

    // ================= GEMM2: K=256 halves, 8 chunks of 32 =================
    float acc2[4][2][4];                 // [m-block][n-8block][elem]
#pragma unroll
    for (int m = 0; m < 4; ++m)
#pragma unroll
        for (int f = 0; f < 2; ++f)
#pragma unroll
            for (int e = 0; e < 4; ++e) acc2[m][f][e] = 0.f;

    const uint4* W2v = (const uint4*)g_W2h;
    const int n2 = tid >> 1, part2 = (tid & 1) * 2;
    for (int c = 0; c < 8; ++c) {
        uint4 pf0, pf1;
        if (c < 7) {
            pf0 = W2v[(c + 1) * 512 + n2 * 4 + part2];
            pf1 = W2v[(c + 1) * 512 + n2 * 4 + part2 + 1];
        }
        const uint32_t Bu = (c & 1) ? sB1_u32 : sB0_u32;
#pragma unroll
        for (int s = 0; s < 2; ++s) {
            const uint32_t kwB = (uint32_t)((c * 16 + s * 8) << 2);
            uint32_t a[4][4];
#pragma unroll
            for (int mb = 0; mb < 4; ++mb)
                LDMX4(a[mb][0], a[mb][1], a[mb][2], a[mb][3],
                      aBase + mb * AMB + kwB);
            uint32_t b00, b01, b10, b11;
            uint32_t baddr = Bu +
                ((((uint32_t)(wid * 16) + bRow) * PBW
                  + (uint32_t)(s * 8) + bWord) << 2);
            LDMX4(b00, b01, b10, b11, baddr);
#pragma unroll
            for (int mb = 0; mb < 4; ++mb) {
                MMA16(acc2[mb][0], a[mb], b00, b01);
                MMA16(acc2[mb][1], a[mb], b10, b11);
            }
        }
        if (c < 7) {
            uint32_t* nbuf = ((c + 1) & 1) ? sB1 : sB0;
            *(uint4*)(nbuf + n2 * PBW + part2 * 4) = pf0;
            *(uint4*)(nbuf + n2 * PBW + (part2 + 1) * 4) = pf1;
        }
        __syncthreads();
    }

    // ---- epilogue 2: out = acc2 + b2 + x ----
#pragma unroll
    for (int mb = 0; mb < 4; ++mb) {
#pragma unroll
        for (int e = 0; e < 2; ++e) {
            int r = mb * 16 + lq + e * 8;
            int node = node0 + r;
            if (node < N) {
#pragma unroll
                for (int f = 0; f < 2; ++f) {
                    int col = wid * 16 + f * 8 + lr * 2;
                    float2 bv = *(const float2*)(b2 + col);
                    float2 xv = *(const float2*)(x + (size_t)node * D_NODE + col);
                    float2 o;
                    o.x = acc2[mb][f][2 * e + 0] + bv.x + xv.x;
                    o.y = acc2[mb][f][2 * e + 1] + bv.y + xv.y;
                    *(float2*)(out + (size_t)node * D_NODE + col) = o;
                }
            }
        }
    }
}

// ---------------------------------------------------------------------------
extern "C" void kernel_launch(void* const* d_in, const int* in_sizes, int n_in,
                              void* d_out, int out_size) {
    const float* x     = (const float*)d_in[0];
    const void*  ei    = d_in[1];
    const float* ea    = (const float*)d_in[2];
    const float* u     = (const float*)d_in[3];
    const void*  batch = d_in[4];
    const float* W1    = (const float*)d_in[5];
    const float* b1    = (const float*)d_in[6];
    const float* W2    = (const float*)d_in[7];
    const float* b2    = (const float*)d_in[8];
    float*       out   = (float*)d_out;

    const int N = in_sizes[0] / D_NODE;   // 100000
    const int E = in_sizes[1] / 2;        // 1600000

    // 1) prep: zero bins + batch + ug + fp16 weight transpose
    int big = (N > NBINS) ? N : NBINS;
    int nb_conv = (big + 255) / 256;
    prep_kernel<<<nb_conv + N_GRAPHS + 32 + 16, 256>>>(ei, batch, u, W1, b1, W2,
                                                       N, nb_conv);

    // 2) fill bins
    fill_kernel<<<(E + 255) / 256, 256>>>(ei, E);

    // 3) aggregation: one warp per bin, no barriers, fp16 out
    int nbins = (N + 7) / 8;
    agg_kernel<<<(nbins + 7) / 8, 256>>>(ea, N);

    // 4) MLP (fp16 mma + ldmatrix, 1Mx8N tiling)
    const int smem_bytes = 18688 * 4;   // 74752 B
    cudaFuncSetAttribute(fused_mlp_mma,
                         cudaFuncAttributeMaxDynamicSharedMemorySize, smem_bytes);
    int tiles = (N + 63) / 64;
    fused_mlp_mma<<<tiles, 256, smem_bytes>>>(x, b2, out, N);
}

// round 17
// speedup vs baseline: 1.1243x; 1.1243x over previous
#include <cuda_runtime.h>
#include <cuda_fp16.h>
#include <cstdint>

#define MAX_NODES 100000
#define D_NODE 128
#define D_HID 256
#define N_GRAPHS 64
#define CAP   320          // per-bin edge capacity (mean 128, sd 11 -> safe)
#define NBINS 12512        // ceil(MAX_NODES/64)*8 rounded up

// Scratch (no cudaMalloc allowed)
__device__ int    g_bin_cnt[NBINS];          // edges per 8-node bin
__device__ int    g_bin_lst[NBINS * CAP];    // packed (edge_id<<3)|(col&7)
__device__ float  g_ug[N_GRAPHS * D_HID];    // u @ W1[256:272] + b1
__device__ int    g_batch[MAX_NODES];        // graph id per node (int32)
__device__ uint2  g_W1f[8 * 2 * 32 * 32];    // W1 frags [c][s][n8][lane] 128KB
__device__ uint2  g_W2f[8 * 2 * 16 * 32];    // W2 frags [c][s][n8][lane]  64KB
__device__ uint4  g_aggh4[MAX_NODES * 16];   // agg as fp16 [node][128] (25.6MB)

// ---------------------------------------------------------------------------
// helpers
// ---------------------------------------------------------------------------
// D += A @ B  (m16n8k16 fp16 operands, fp32 accum)
#define MMA16(d, a, b0_, b1_)                                                  \
    asm volatile(                                                              \
        "mma.sync.aligned.m16n8k16.row.col.f32.f16.f16.f32 "                   \
        "{%0,%1,%2,%3}, {%4,%5,%6,%7}, {%8,%9}, {%0,%1,%2,%3};"                \
        : "+f"((d)[0]), "+f"((d)[1]), "+f"((d)[2]), "+f"((d)[3])               \
        : "r"((a)[0]), "r"((a)[1]), "r"((a)[2]), "r"((a)[3]),                  \
          "r"(b0_), "r"(b1_))

// 4x 8x8 fp16 tiles from shared (sm_75+ baseline)
#define LDMX4(r0, r1, r2, r3, addr)                                            \
    asm volatile(                                                              \
        "ldmatrix.sync.aligned.m8n8.x4.shared.b16 {%0,%1,%2,%3}, [%4];"        \
        : "=r"(r0), "=r"(r1), "=r"(r2), "=r"(r3) : "r"(addr))

__device__ __forceinline__ uint32_t pack2(float a, float b) {
    __half2 h = __floats2half2_rn(a, b);          // x=a (low), y=b (high)
    return *(uint32_t*)&h;
}

// SMEM pitch in 32-bit words. PAW=132: ldmatrix A phases conflict-free.
#define PAW 132

// per-block int64-vs-int32 detect: odd 32-bit words of first 128 int64s are 0
__device__ __forceinline__ int detect_is64(const unsigned* w, int tid, int* s_flag) {
    if (tid < 32) {
        unsigned bad = 0;
#pragma unroll
        for (int j = 0; j < 4; ++j) bad |= w[8 * tid + 2 * j + 1];
        unsigned any = __ballot_sync(0xffffffffu, bad != 0u);
        if (tid == 0) *s_flag = (any == 0u);
    }
    __syncthreads();
    return *s_flag;
}

// ---------------------------------------------------------------------------
// Kernel 1: prep = zero bins + batch + ug + W fragment-order fp16 transform
// Fragment layout: word0 = halves (k=2q0, 2q0+1), word1 = (2q1, 2q1+1) at
// column n = n8*8+lq, q0 = s*8+lr, q1 = q0+4 — exactly the b0/b1 the mma
// lanes consume (bit-identical to the old SMEM path).
// ---------------------------------------------------------------------------
__global__ void prep_kernel(const void* __restrict__ ei,
                            const void* __restrict__ batch,
                            const float* __restrict__ u,
                            const float* __restrict__ W1,
                            const float* __restrict__ b1,
                            const float* __restrict__ W2,
                            int N, int nb_conv) {
    __shared__ int s_flag;
    const int bx = blockIdx.x;
    const int tid = threadIdx.x;
    if (bx < nb_conv) {                               // bins + batch
        int is64 = detect_is64((const unsigned*)ei, tid, &s_flag);
        int i = bx * 256 + tid;
        if (i < NBINS) g_bin_cnt[i] = 0;
        if (i < N)
            g_batch[i] = is64 ? (int)((const long long*)batch)[i]
                              : ((const int*)batch)[i];
    } else if (bx < nb_conv + N_GRAPHS) {             // ug
        int g = bx - nb_conv, n = tid;
        float s = b1[n];
#pragma unroll
        for (int k = 0; k < 16; ++k)
            s += u[g * 16 + k] * W1[(256 + k) * D_HID + n];
        g_ug[g * D_HID + n] = s;
    } else if (bx < nb_conv + N_GRAPHS + 64) {        // W1 fragments
        int j = (bx - nb_conv - N_GRAPHS) * 256 + tid;   // 0..16383
        int c = j >> 11;
        int s = (j >> 10) & 1;
        int n8 = (j >> 5) & 31;
        int lane = j & 31;
        int lq = lane >> 2, lr = lane & 3;
        int n = n8 * 8 + lq;
        int q0 = s * 8 + lr, q1 = q0 + 4;
        int k0 = c * 32;
        uint2 w;
        w.x = pack2(W1[(size_t)(k0 + 2 * q0) * D_HID + n],
                    W1[(size_t)(k0 + 2 * q0 + 1) * D_HID + n]);
        w.y = pack2(W1[(size_t)(k0 + 2 * q1) * D_HID + n],
                    W1[(size_t)(k0 + 2 * q1 + 1) * D_HID + n]);
        g_W1f[j] = w;
    } else {                                          // W2 fragments
        int j = (bx - nb_conv - N_GRAPHS - 64) * 256 + tid;  // 0..8191
        int c = j >> 10;
        int s = (j >> 9) & 1;
        int n8 = (j >> 5) & 15;
        int lane = j & 31;
        int lq = lane >> 2, lr = lane & 3;
        int n = n8 * 8 + lq;
        int q0 = s * 8 + lr, q1 = q0 + 4;
        int k0 = c * 32;
        uint2 w;
        w.x = pack2(W2[(size_t)(k0 + 2 * q0) * D_NODE + n],
                    W2[(size_t)(k0 + 2 * q0 + 1) * D_NODE + n]);
        w.y = pack2(W2[(size_t)(k0 + 2 * q1) * D_NODE + n],
                    W2[(size_t)(k0 + 2 * q1 + 1) * D_NODE + n]);
        g_W2f[j] = w;
    }
}

// ---------------------------------------------------------------------------
// Kernel 2: fill bins. One thread per edge.
// ---------------------------------------------------------------------------
__global__ void fill_kernel(const void* __restrict__ ei, int E) {
    __shared__ int s_flag;
    int is64 = detect_is64((const unsigned*)ei, threadIdx.x, &s_flag);
    int i = blockIdx.x * 256 + threadIdx.x;
    if (i >= E) return;
    int col = is64 ? (int)((const long long*)ei)[(long long)E + i]
                   : ((const int*)ei)[E + i];
    int b = col >> 3;
    int pos = atomicAdd(&g_bin_cnt[b], 1);
    if (pos < CAP) g_bin_lst[b * CAP + pos] = (i << 3) | (col & 7);
}

// ===========================================================================
// Kernel 3: dedicated aggregation (R15 exact). One warp per 8-node bin,
// spill-proof depth-8 pipeline, no __syncthreads, fp16 out.
// ===========================================================================
__global__ void __launch_bounds__(256)
agg_kernel(const float* __restrict__ ea, int N) {
    __shared__ float sAgg[8 * 8 * 128];          // 8 warps x 8 rows x 128
    const int lane = threadIdx.x & 31;
    const int wid  = threadIdx.x >> 5;
    const int bin  = blockIdx.x * 8 + wid;
    const int nbins = (N + 7) >> 3;
    if (bin >= nbins) return;

    float* myAgg = sAgg + wid * 8 * 128;
#pragma unroll
    for (int r = 0; r < 8; ++r)
        *(float4*)(myAgg + r * 128 + lane * 4) = make_float4(0.f, 0.f, 0.f, 0.f);

    int cnt = g_bin_cnt[bin];
    if (cnt > CAP) cnt = CAP;
    const int* lst = g_bin_lst + (size_t)bin * CAP;

    float4 vb[8]; int rb[8];
#pragma unroll
    for (int j = 0; j < 8; ++j)
        if (j < cnt) {
            int p = lst[j];
            rb[j] = p & 7;
            vb[j] = ((const float4*)ea)[(size_t)(p >> 3) * 32 + lane];
        }
    int i = 0;
    for (; i + 8 <= cnt; i += 8) {
#pragma unroll
        for (int j = 0; j < 8; ++j) {
            float4 v = vb[j];
            int    r = rb[j];
            int nidx = i + 8 + j;
            if (nidx < cnt) {
                int p = lst[nidx];
                rb[j] = p & 7;
                vb[j] = ((const float4*)ea)[(size_t)(p >> 3) * 32 + lane];
            }
            float* d = myAgg + r * 128 + lane * 4;
            float4 o = *(float4*)d;
            o.x += v.x; o.y += v.y; o.z += v.z; o.w += v.w;
            *(float4*)d = o;
        }
    }
#pragma unroll
    for (int j = 0; j < 8; ++j) {
        if (i + j < cnt) {
            float4 v = vb[j];
            float* d = myAgg + rb[j] * 128 + lane * 4;
            float4 o = *(float4*)d;
            o.x += v.x; o.y += v.y; o.z += v.z; o.w += v.w;
            *(float4*)d = o;
        }
    }
#pragma unroll
    for (int r = 0; r < 8; ++r) {
        int node = bin * 8 + r;
        if (node < N) {
            float4 o = *(float4*)(myAgg + r * 128 + lane * 4);
            uint2 h;
            h.x = pack2(o.x, o.y);
            h.y = pack2(o.z, o.w);
            ((uint2*)g_aggh4)[(size_t)node * 32 + lane] = h;
        }
    }
}

// ===========================================================================
// Kernel 4: MLP, fp16 mma. A from SMEM via ldmatrix (R15 2Mx4N tiling);
// B fragments DIRECT FROM GMEM (g_W1f/g_W2f, L1-resident, one uint2 LDG per
// fragment). No B smem buffers, no W staging, and only 3 __syncthreads in
// the whole kernel — warps run the K loops unsynchronized.
//   GEMM1: h = relu([x|agg] @ W1[0:256] + ug[batch])  warp tile 32x64
//   GEMM2: out = h @ W2 + b2 + x                      warp tile 32x32
// ===========================================================================
__global__ void __launch_bounds__(256, 2)
fused_mlp_mma(const float* __restrict__ x,
              const float* __restrict__ b2,
              float* __restrict__ out, int N) {
    extern __shared__ uint32_t smw[];
    uint32_t* sAw = smw;                        // A fp16: 64 rows x 132 words
    __shared__ int s_batch[64];

    const int tid  = threadIdx.x;
    const int lane = tid & 31;
    const int wid  = tid >> 5;       // 0..7
    const int wm   = wid >> 2;       // 0..1
    const int wn   = wid & 3;        // 0..3
    const int lq   = lane >> 2;      // 0..7
    const int lr   = lane & 3;       // 0..3
    const int node0 = blockIdx.x * 64;

    const uint32_t sA_u32 = (uint32_t)__cvta_generic_to_shared(sAw);
    const uint32_t aBase0 = sA_u32 +
        (((uint32_t)(wm * 32 + (lane & 15)) * PAW + ((lane >> 4) * 4)) << 2);
    const uint32_t aBase1 = aBase0 + (16 * PAW << 2);

    if (tid < 64) s_batch[tid] = (node0 + tid < N) ? g_batch[node0 + tid] : 0;

    // ---- stage x -> sA words [0,64) per row, RNE fp16 ----
#pragma unroll
    for (int j = 0; j < 4; ++j) {
        int idx = tid + j * 256;          // 0..1023
        int row = idx >> 4, wq = idx & 15;
        int node = node0 + row;
        float4 v0 = make_float4(0.f, 0.f, 0.f, 0.f), v1 = v0;
        if (node < N) {
            v0 = ((const float4*)x)[(size_t)node * 32 + wq * 2];
            v1 = ((const float4*)x)[(size_t)node * 32 + wq * 2 + 1];
        }
        uint4 h;
        h.x = pack2(v0.x, v0.y); h.y = pack2(v0.z, v0.w);
        h.z = pack2(v1.x, v1.y); h.w = pack2(v1.z, v1.w);
        *(uint4*)(sAw + row * PAW + wq * 4) = h;
    }

    // ---- stage agg (already fp16) -> sA words [64,128) per row ----
#pragma unroll
    for (int j = 0; j < 4; ++j) {
        int idx = tid + j * 256;          // 0..1023
        int row = idx >> 4, q = idx & 15;
        int node = node0 + row;
        uint4 v = make_uint4(0u, 0u, 0u, 0u);
        if (node < N) v = g_aggh4[(size_t)node * 16 + q];
        *(uint4*)(sAw + row * PAW + 64 + q * 4) = v;
    }
    __syncthreads();                                   // A tile published

    // ================= GEMM1: K=256, 8 chunks of 32, no barriers ============
    float acc[2][8][4];
#pragma unroll
    for (int m = 0; m < 2; ++m)
#pragma unroll
        for (int f = 0; f < 8; ++f)
#pragma unroll
            for (int e = 0; e < 4; ++e) acc[m][f][e] = 0.f;

    for (int c = 0; c < 8; ++c) {
#pragma unroll
        for (int s = 0; s < 2; ++s) {
            const uint32_t kwB = (uint32_t)((c * 16 + s * 8) << 2);
            uint32_t a0[4], a1[4];
            LDMX4(a0[0], a0[1], a0[2], a0[3], aBase0 + kwB);
            LDMX4(a1[0], a1[1], a1[2], a1[3], aBase1 + kwB);
            const uint2* Bf = g_W1f +
                ((size_t)(c * 2 + s) * 32 + wn * 8) * 32 + lane;
#pragma unroll
            for (int f = 0; f < 8; ++f) {
                uint2 bw = Bf[f * 32];
                MMA16(acc[0][f], a0, bw.x, bw.y);
                MMA16(acc[1][f], a1, bw.x, bw.y);
            }
        }
    }
    __syncthreads();                                   // all A reads complete

    // ---- epilogue 1: h = relu(acc + ug[batch]) -> sA (fp16) ----
#pragma unroll
    for (int mb = 0; mb < 2; ++mb) {
#pragma unroll
        for (int e = 0; e < 2; ++e) {
            int r = wm * 32 + mb * 16 + lq + e * 8;
            int g = s_batch[r];
            const float* ugr = g_ug + g * D_HID;
#pragma unroll
            for (int f = 0; f < 8; ++f) {
                int col = wn * 64 + f * 8 + lr * 2;
                float2 ug = *(const float2*)(ugr + col);
                float h0 = fmaxf(acc[mb][f][2 * e + 0] + ug.x, 0.f);
                float h1 = fmaxf(acc[mb][f][2 * e + 1] + ug.y, 0.f);
                sAw[r * PAW + wn * 32 + f * 4 + lr] = pack2(h0, h1);
            }
        }
    }
    __syncthreads();                                   // h published

    // ================= GEMM2: K=256, 8 chunks of 32, no barriers ============
    float acc2[2][4][4];
#pragma unroll
    for (int m = 0; m < 2; ++m)
#pragma unroll
        for (int f = 0; f < 4; ++f)
#pragma unroll
            for (int e = 0; e < 4; ++e) acc2[m][f][e] = 0.f;

    for (int c = 0; c < 8; ++c) {
#pragma unroll
        for (int s = 0; s < 2; ++s) {
            const uint32_t kwB = (uint32_t)((c * 16 + s * 8) << 2);
            uint32_t a0[4], a1[4];
            LDMX4(a0[0], a0[1], a0[2], a0[3], aBase0 + kwB);
            LDMX4(a1[0], a1[1], a1[2], a1[3], aBase1 + kwB);
            const uint2* Bf = g_W2f +
                ((size_t)(c * 2 + s) * 16 + wn * 4) * 32 + lane;
#pragma unroll
            for (int f = 0; f < 4; ++f) {
                uint2 bw = Bf[f * 32];
                MMA16(acc2[0][f], a0, bw.x, bw.y);
                MMA16(acc2[1][f], a1, bw.x, bw.y);
            }
        }
    }

    // ---- epilogue 2: out = acc2 + b2 + x ----
#pragma unroll
    for (int mb = 0; mb < 2; ++mb) {
#pragma unroll
        for (int e = 0; e < 2; ++e) {
            int r = wm * 32 + mb * 16 + lq + e * 8;
            int node = node0 + r;
            if (node < N) {
#pragma unroll
                for (int f = 0; f < 4; ++f) {
                    int col = wn * 32 + f * 8 + lr * 2;
                    float2 bv = *(const float2*)(b2 + col);
                    float2 xv = *(const float2*)(x + (size_t)node * D_NODE + col);
                    float2 o;
                    o.x = acc2[mb][f][2 * e + 0] + bv.x + xv.x;
                    o.y = acc2[mb][f][2 * e + 1] + bv.y + xv.y;
                    *(float2*)(out + (size_t)node * D_NODE + col) = o;
                }
            }
        }
    }
}

// ---------------------------------------------------------------------------
extern "C" void kernel_launch(void* const* d_in, const int* in_sizes, int n_in,
                              void* d_out, int out_size) {
    const float* x     = (const float*)d_in[0];
    const void*  ei    = d_in[1];
    const float* ea    = (const float*)d_in[2];
    const float* u     = (const float*)d_in[3];
    const void*  batch = d_in[4];
    const float* W1    = (const float*)d_in[5];
    const float* b1    = (const float*)d_in[6];
    const float* W2    = (const float*)d_in[7];
    const float* b2    = (const float*)d_in[8];
    float*       out   = (float*)d_out;

    const int N = in_sizes[0] / D_NODE;   // 100000
    const int E = in_sizes[1] / 2;        // 1600000

    // 1) prep: zero bins + batch + ug + W fragment transform
    int big = (N > NBINS) ? N : NBINS;
    int nb_conv = (big + 255) / 256;
    prep_kernel<<<nb_conv + N_GRAPHS + 64 + 32, 256>>>(ei, batch, u, W1, b1, W2,
                                                       N, nb_conv);

    // 2) fill bins
    fill_kernel<<<(E + 255) / 256, 256>>>(ei, E);

    // 3) aggregation: one warp per bin, no barriers, fp16 out
    int nbins = (N + 7) / 8;
    agg_kernel<<<(nbins + 7) / 8, 256>>>(ea, N);

    // 4) MLP (fp16 mma, B fragments direct from gmem, 3 barriers total)
    const int smem_bytes = 8448 * 4;   // 33792 B (A tile only)
    cudaFuncSetAttribute(fused_mlp_mma,
                         cudaFuncAttributeMaxDynamicSharedMemorySize, smem_bytes);
    int tiles = (N + 63) / 64;
    fused_mlp_mma<<<tiles, 256, smem_bytes>>>(x, b2, out, N);
}